// round 4
// baseline (speedup 1.0000x reference)
#include <cuda_runtime.h>
#include <math.h>

// Problem constants
#define BB   16
#define CC   256
#define HH   48
#define WW   48
#define NN   2304          // H*W
#define KTOT 2304          // C*9 for 3x3 conv implicit GEMM
#define EPSB 1e-5f

// ---------------------------------------------------------------------------
// Scratch (device globals; allocation-free per harness rules)
// ---------------------------------------------------------------------------
__device__ float g_Q    [(size_t)BB * CC * NN];
__device__ float g_K    [(size_t)BB * CC * NN];
__device__ float g_V    [(size_t)BB * CC * NN];
__device__ float g_fused[(size_t)BB * CC * NN];
__device__ float g_tmp  [(size_t)BB * CC * NN];
__device__ float g_attn [(size_t)BB * NN * NN];

// ---------------------------------------------------------------------------
// Tile config: 128x128 block tile, BK=8, 256 threads, 8x8 per thread
// ---------------------------------------------------------------------------
#define BM 128
#define BN 128
#define BK 8

// ===========================================================================
// Kernel 1: Q/K/V 1x1 conv.  Out[b,o,n] = sum_c W[o,c]*X[b,c,n] + bias[o]
// grid: (NN/128, CC/128, BB)
// ===========================================================================
__global__ __launch_bounds__(256) void k_qkv(
    const float* __restrict__ Wt, const float* __restrict__ bias,
    const float* __restrict__ X, float* __restrict__ Out)
{
    const int bz = blockIdx.z;
    const float* Xb = X   + (size_t)bz * CC * NN;
    float*       Ob = Out + (size_t)bz * CC * NN;
    const int rowT = blockIdx.y * BM;
    const int colT = blockIdx.x * BN;

    __shared__ float As[BK][BM];
    __shared__ float Bs[BK][BN];

    const int tid  = threadIdx.x;
    const int aRow = tid >> 1;           // 0..127
    const int aCol = (tid & 1) << 2;     // 0 or 4
    const int bRow = tid >> 5;           // 0..7
    const int bCol = (tid & 31) << 2;    // 0..124
    const int tr   = (tid >> 4) << 3;
    const int tc   = (tid & 15) << 3;

    float acc[8][8] = {};

    for (int k0 = 0; k0 < CC; k0 += BK) {
        float4 av = *(const float4*)(Wt + (size_t)(rowT + aRow) * CC + k0 + aCol);
        As[aCol + 0][aRow] = av.x; As[aCol + 1][aRow] = av.y;
        As[aCol + 2][aRow] = av.z; As[aCol + 3][aRow] = av.w;
        *(float4*)(&Bs[bRow][bCol]) =
            *(const float4*)(Xb + (size_t)(k0 + bRow) * NN + colT + bCol);
        __syncthreads();
        #pragma unroll
        for (int k = 0; k < BK; k++) {
            float ra[8], rb[8];
            #pragma unroll
            for (int i = 0; i < 8; i++) ra[i] = As[k][tr + i];
            #pragma unroll
            for (int j = 0; j < 8; j++) rb[j] = Bs[k][tc + j];
            #pragma unroll
            for (int i = 0; i < 8; i++)
                #pragma unroll
                for (int j = 0; j < 8; j++)
                    acc[i][j] = fmaf(ra[i], rb[j], acc[i][j]);
        }
        __syncthreads();
    }
    #pragma unroll
    for (int i = 0; i < 8; i++) {
        const float bv = bias[rowT + tr + i];
        float* dst = Ob + (size_t)(rowT + tr + i) * NN + colT + tc;
        #pragma unroll
        for (int j = 0; j < 8; j++) dst[j] = acc[i][j] + bv;
    }
}

// ===========================================================================
// Kernel 2: scores[b,n,m] = sum_c K[b,c,n] * Q[b,c,m]
// grid: (NN/128 (m), NN/128 (n), BB)
// ===========================================================================
__global__ __launch_bounds__(256) void k_scores(
    const float* __restrict__ Kt, const float* __restrict__ Qt,
    float* __restrict__ S)
{
    const int bz = blockIdx.z;
    const float* Kb = Kt + (size_t)bz * CC * NN;
    const float* Qb = Qt + (size_t)bz * CC * NN;
    float*       Sb = S  + (size_t)bz * NN * NN;
    const int rowT = blockIdx.y * BM;   // n
    const int colT = blockIdx.x * BN;   // m

    __shared__ float As[BK][BM];
    __shared__ float Bs[BK][BN];

    const int tid = threadIdx.x;
    const int lK  = tid >> 5;           // 0..7 (k within chunk)
    const int lM  = (tid & 31) << 2;    // 0..124
    const int tr  = (tid >> 4) << 3;
    const int tc  = (tid & 15) << 3;

    float acc[8][8] = {};

    for (int k0 = 0; k0 < CC; k0 += BK) {
        // A tile: K[c, n] contiguous along n -> directly [k][m] layout
        *(float4*)(&As[lK][lM]) =
            *(const float4*)(Kb + (size_t)(k0 + lK) * NN + rowT + lM);
        *(float4*)(&Bs[lK][lM]) =
            *(const float4*)(Qb + (size_t)(k0 + lK) * NN + colT + lM);
        __syncthreads();
        #pragma unroll
        for (int k = 0; k < BK; k++) {
            float ra[8], rb[8];
            #pragma unroll
            for (int i = 0; i < 8; i++) ra[i] = As[k][tr + i];
            #pragma unroll
            for (int j = 0; j < 8; j++) rb[j] = Bs[k][tc + j];
            #pragma unroll
            for (int i = 0; i < 8; i++)
                #pragma unroll
                for (int j = 0; j < 8; j++)
                    acc[i][j] = fmaf(ra[i], rb[j], acc[i][j]);
        }
        __syncthreads();
    }
    #pragma unroll
    for (int i = 0; i < 8; i++) {
        float* dst = Sb + (size_t)(rowT + tr + i) * NN + colT + tc;
        #pragma unroll
        for (int j = 0; j < 8; j++) dst[j] = acc[i][j];
    }
}

// ===========================================================================
// Kernel 3: row softmax over last axis (rows of length NN), in place.
// grid: BB*NN blocks, 256 threads. 9 elems per thread register-resident.
// ===========================================================================
__global__ __launch_bounds__(256) void k_softmax(float* __restrict__ A)
{
    float* p = A + (size_t)blockIdx.x * NN;
    const int tid = threadIdx.x;
    float v[9];
    float mx = -1e30f;
    #pragma unroll
    for (int i = 0; i < 9; i++) {
        v[i] = p[tid + (i << 8)];
        mx = fmaxf(mx, v[i]);
    }
    __shared__ float red[8];
    #pragma unroll
    for (int o = 16; o > 0; o >>= 1)
        mx = fmaxf(mx, __shfl_xor_sync(0xffffffffu, mx, o));
    if ((tid & 31) == 0) red[tid >> 5] = mx;
    __syncthreads();
    float m2 = red[0];
    #pragma unroll
    for (int i = 1; i < 8; i++) m2 = fmaxf(m2, red[i]);
    __syncthreads();

    float s = 0.f;
    #pragma unroll
    for (int i = 0; i < 9; i++) {
        v[i] = __expf(v[i] - m2);
        s += v[i];
    }
    #pragma unroll
    for (int o = 16; o > 0; o >>= 1)
        s += __shfl_xor_sync(0xffffffffu, s, o);
    if ((tid & 31) == 0) red[tid >> 5] = s;
    __syncthreads();
    float s2 = 0.f;
    #pragma unroll
    for (int i = 0; i < 8; i++) s2 += red[i];
    const float inv = 1.0f / s2;
    #pragma unroll
    for (int i = 0; i < 9; i++) p[tid + (i << 8)] = v[i] * inv;
}

// ===========================================================================
// Kernel 4: fused[b,c,m] = F_b[b,c,m] + sum_n V[b,c,n] * attn[b,n,m]
// grid: (NN/128, CC/128, BB).  K-dim = NN.
// ===========================================================================
__global__ __launch_bounds__(256) void k_av(
    const float* __restrict__ Vt, const float* __restrict__ At,
    const float* __restrict__ Fb, float* __restrict__ Out)
{
    const int bz = blockIdx.z;
    const float* Vb = Vt  + (size_t)bz * CC * NN;
    const float* Ab = At  + (size_t)bz * NN * NN;
    const float* Rb = Fb  + (size_t)bz * CC * NN;
    float*       Ob = Out + (size_t)bz * CC * NN;
    const int rowT = blockIdx.y * BM;   // c
    const int colT = blockIdx.x * BN;   // m

    __shared__ float As[BK][BM];
    __shared__ float Bs[BK][BN];

    const int tid  = threadIdx.x;
    const int aRow = tid >> 1;
    const int aCol = (tid & 1) << 2;
    const int bRow = tid >> 5;
    const int bCol = (tid & 31) << 2;
    const int tr   = (tid >> 4) << 3;
    const int tc   = (tid & 15) << 3;

    float acc[8][8] = {};

    for (int k0 = 0; k0 < NN; k0 += BK) {
        float4 av = *(const float4*)(Vb + (size_t)(rowT + aRow) * NN + k0 + aCol);
        As[aCol + 0][aRow] = av.x; As[aCol + 1][aRow] = av.y;
        As[aCol + 2][aRow] = av.z; As[aCol + 3][aRow] = av.w;
        *(float4*)(&Bs[bRow][bCol]) =
            *(const float4*)(Ab + (size_t)(k0 + bRow) * NN + colT + bCol);
        __syncthreads();
        #pragma unroll
        for (int k = 0; k < BK; k++) {
            float ra[8], rb[8];
            #pragma unroll
            for (int i = 0; i < 8; i++) ra[i] = As[k][tr + i];
            #pragma unroll
            for (int j = 0; j < 8; j++) rb[j] = Bs[k][tc + j];
            #pragma unroll
            for (int i = 0; i < 8; i++)
                #pragma unroll
                for (int j = 0; j < 8; j++)
                    acc[i][j] = fmaf(ra[i], rb[j], acc[i][j]);
        }
        __syncthreads();
    }
    #pragma unroll
    for (int i = 0; i < 8; i++) {
        const float* res = Rb + (size_t)(rowT + tr + i) * NN + colT + tc;
        float*       dst = Ob + (size_t)(rowT + tr + i) * NN + colT + tc;
        #pragma unroll
        for (int j = 0; j < 8; j++) dst[j] = acc[i][j] + res[j];
    }
}

// ===========================================================================
// Kernel 5/6: implicit-GEMM 3x3 SAME conv + BN (+relu / +residual epilogue)
// Out[b,o,p] = bn( sum_{c,ky,kx} W[o,c,ky,kx] * In[b,c,y+ky-1,x+kx-1] )
// grid: (NN/128, CC/128, BB). K-dim = C*9 = 2304.
// SECOND=false : out = relu(bn(acc))
// SECOND=true  : f = Res; out = relu(bn(acc) + f) + f
// ===========================================================================
template <bool SECOND>
__global__ __launch_bounds__(256) void k_conv(
    const float* __restrict__ Wt, const float* __restrict__ In,
    const float* __restrict__ bn_s, const float* __restrict__ bn_b,
    const float* __restrict__ bn_m, const float* __restrict__ bn_v,
    const float* __restrict__ Res, float* __restrict__ Out)
{
    const int bz = blockIdx.z;
    const float* Inb = In  + (size_t)bz * CC * NN;
    float*       Ob  = Out + (size_t)bz * CC * NN;
    const int rowT = blockIdx.y * BM;   // o
    const int colT = blockIdx.x * BN;   // p (spatial)

    __shared__ float As[BK][BM];
    __shared__ float Bs[BK][BN];

    const int tid  = threadIdx.x;
    const int aRow = tid >> 1;
    const int aCol = (tid & 1) << 2;
    const int bK   = tid >> 5;          // 0..7
    const int bP   = (tid & 31) << 2;   // 0..124
    const int tr   = (tid >> 4) << 3;
    const int tc   = (tid & 15) << 3;

    // spatial coords for this thread's B-loads (constant over k loop;
    // float4 never crosses an image row since 48 % 4 == 0)
    const int p = colT + bP;
    const int y = p / WW;
    const int x = p - y * WW;

    float acc[8][8] = {};

    for (int k0 = 0; k0 < KTOT; k0 += BK) {
        float4 av = *(const float4*)(Wt + (size_t)(rowT + aRow) * KTOT + k0 + aCol);
        As[aCol + 0][aRow] = av.x; As[aCol + 1][aRow] = av.y;
        As[aCol + 2][aRow] = av.z; As[aCol + 3][aRow] = av.w;

        // im2col on the fly: k = c*9 + ky*3 + kx
        {
            const int kk = k0 + bK;
            const int c  = kk / 9;
            const int r  = kk - c * 9;
            const int ky = r / 3;
            const int kx = r - ky * 3;
            const int sy = y + ky - 1;
            const bool yok = (unsigned)sy < (unsigned)HH;
            const float* src = Inb + (size_t)c * NN + sy * WW;
            #pragma unroll
            for (int u = 0; u < 4; u++) {
                const int sx = x + u + kx - 1;
                Bs[bK][bP + u] =
                    (yok && (unsigned)sx < (unsigned)WW) ? src[sx] : 0.0f;
            }
        }
        __syncthreads();
        #pragma unroll
        for (int k = 0; k < BK; k++) {
            float ra[8], rb[8];
            #pragma unroll
            for (int i = 0; i < 8; i++) ra[i] = As[k][tr + i];
            #pragma unroll
            for (int j = 0; j < 8; j++) rb[j] = Bs[k][tc + j];
            #pragma unroll
            for (int i = 0; i < 8; i++)
                #pragma unroll
                for (int j = 0; j < 8; j++)
                    acc[i][j] = fmaf(ra[i], rb[j], acc[i][j]);
        }
        __syncthreads();
    }

    #pragma unroll
    for (int i = 0; i < 8; i++) {
        const int o = rowT + tr + i;
        const float inv  = bn_s[o] * rsqrtf(bn_v[o] + EPSB);
        const float beta = bn_b[o] - bn_m[o] * inv;
        float*       dst = Ob + (size_t)o * NN + colT + tc;
        const float* res = SECOND ? (Res + (size_t)bz * CC * NN
                                         + (size_t)o * NN + colT + tc)
                                  : nullptr;
        #pragma unroll
        for (int j = 0; j < 8; j++) {
            float val = acc[i][j] * inv + beta;
            if (SECOND) {
                const float f = res[j];
                val = fmaxf(val + f, 0.0f) + f;
            } else {
                val = fmaxf(val, 0.0f);
            }
            dst[j] = val;
        }
    }
}

// ===========================================================================
// Host launcher
// ===========================================================================
extern "C" void kernel_launch(void* const* d_in, const int* in_sizes, int n_in,
                              void* d_out, int out_size)
{
    (void)in_sizes; (void)n_in; (void)out_size;
    const float* F_b  = (const float*)d_in[0];
    const float* F_a  = (const float*)d_in[1];
    const float* qw   = (const float*)d_in[2];
    const float* qb   = (const float*)d_in[3];
    const float* kw   = (const float*)d_in[4];
    const float* kb   = (const float*)d_in[5];
    const float* vw   = (const float*)d_in[6];
    const float* vb   = (const float*)d_in[7];
    const float* c1w  = (const float*)d_in[8];
    const float* bn1s = (const float*)d_in[9];
    const float* bn1b = (const float*)d_in[10];
    const float* bn1m = (const float*)d_in[11];
    const float* bn1v = (const float*)d_in[12];
    const float* c2w  = (const float*)d_in[13];
    const float* bn2s = (const float*)d_in[14];
    const float* bn2b = (const float*)d_in[15];
    const float* bn2m = (const float*)d_in[16];
    const float* bn2v = (const float*)d_in[17];
    float* out = (float*)d_out;

    float *Q, *K, *V, *fused, *tmp, *attn;
    cudaGetSymbolAddress((void**)&Q,     g_Q);
    cudaGetSymbolAddress((void**)&K,     g_K);
    cudaGetSymbolAddress((void**)&V,     g_V);
    cudaGetSymbolAddress((void**)&fused, g_fused);
    cudaGetSymbolAddress((void**)&tmp,   g_tmp);
    cudaGetSymbolAddress((void**)&attn,  g_attn);

    dim3 blk(256);
    dim3 gFeat(NN / BN, CC / BM, BB);   // (18, 2, 16)
    dim3 gScor(NN / BN, NN / BM, BB);   // (18, 18, 16)

    k_qkv<<<gFeat, blk>>>(qw, qb, F_b, Q);
    k_qkv<<<gFeat, blk>>>(kw, kb, F_a, K);
    k_qkv<<<gFeat, blk>>>(vw, vb, F_a, V);
    k_scores<<<gScor, blk>>>(K, Q, attn);
    k_softmax<<<BB * NN, 256>>>(attn);
    k_av<<<gFeat, blk>>>(V, attn, F_b, fused);
    k_conv<false><<<gFeat, blk>>>(c1w, fused, bn1s, bn1b, bn1m, bn1v,
                                  nullptr, tmp);
    k_conv<true><<<gFeat, blk>>>(c2w, tmp, bn2s, bn2b, bn2m, bn2v,
                                 fused, out);
}

// round 6
// speedup vs baseline: 2.1764x; 2.1764x over previous
#include <cuda_runtime.h>
#include <cuda_bf16.h>
#include <cstdint>

#define BBATCH 16
#define CCH    256
#define HHH    48
#define WWW    48
#define NPIX   2304
#define KCONV  2304
#define EPSB   1e-5f

#define BMT 128
#define BNT 128
#define BKT 32

#define AK_PAD 40     // A [m][k]: 40 bf16/row = 80B
#define N_PAD  136    // [k][n]:  136 bf16/row = 272B

// ---------------- scratch ----------------
__device__ float g_Q    [(size_t)BBATCH * CCH * NPIX];
__device__ float g_K    [(size_t)BBATCH * CCH * NPIX];
__device__ float g_V    [(size_t)BBATCH * CCH * NPIX];
__device__ float g_fused[(size_t)BBATCH * CCH * NPIX];
__device__ float g_tmp  [(size_t)BBATCH * CCH * NPIX];
__device__ float g_attn [(size_t)BBATCH * NPIX * NPIX];

// ---------------- helpers ----------------
__device__ __forceinline__ uint32_t smem_u32(const void* p) {
    uint32_t a;
    asm("{ .reg .u64 t; cvta.to.shared.u64 t, %1; cvt.u32.u64 %0, t; }"
        : "=r"(a) : "l"(p));
    return a;
}
__device__ __forceinline__ uint32_t pk(__nv_bfloat16 a, __nv_bfloat16 b) {
    return (uint32_t)__bfloat16_as_ushort(a) |
           ((uint32_t)__bfloat16_as_ushort(b) << 16);
}
__device__ __forceinline__ void spl(float x, __nv_bfloat16& h, __nv_bfloat16& l) {
    h = __float2bfloat16(x);
    l = __float2bfloat16(x - __bfloat162float(h));
}
// pack float4 -> hi uint2 / lo uint2
__device__ __forceinline__ void cvt_sts4(char* hi, char* lo, uint32_t off, float4 v) {
    __nv_bfloat16 h0,l0,h1,l1,h2,l2,h3,l3;
    spl(v.x,h0,l0); spl(v.y,h1,l1); spl(v.z,h2,l2); spl(v.w,h3,l3);
    *(uint2*)(hi + off) = make_uint2(pk(h0,h1), pk(h2,h3));
    *(uint2*)(lo + off) = make_uint2(pk(l0,l1), pk(l2,l3));
}

#define LDMX4(R, addr) \
    asm volatile("ldmatrix.sync.aligned.m8n8.x4.shared.b16 {%0,%1,%2,%3}, [%4];" \
        : "=r"((R)[0]), "=r"((R)[1]), "=r"((R)[2]), "=r"((R)[3]) : "r"(addr))
#define LDMX4T(R, addr) \
    asm volatile("ldmatrix.sync.aligned.m8n8.x4.trans.shared.b16 {%0,%1,%2,%3}, [%4];" \
        : "=r"((R)[0]), "=r"((R)[1]), "=r"((R)[2]), "=r"((R)[3]) : "r"(addr))
#define MMA16816(d, a, b) \
    asm volatile("mma.sync.aligned.m16n8k16.row.col.f32.bf16.bf16.f32 " \
        "{%0,%1,%2,%3}, {%4,%5,%6,%7}, {%8,%9}, {%0,%1,%2,%3};" \
        : "+f"((d)[0]), "+f"((d)[1]), "+f"((d)[2]), "+f"((d)[3]) \
        : "r"((a)[0]), "r"((a)[1]), "r"((a)[2]), "r"((a)[3]), \
          "r"((b)[0]), "r"((b)[1]))

enum { E_NONE = 0, E_BROW = 1, E_RES = 2, E_BN = 3, E_BNRES = 4 };

// ===========================================================================
// Unified HMMA GEMM: D[m][n] = sum_k A[m][k] * B[k][n]   (128x128x32 tiles)
//   TA=false: A source row-major [m][k] (lda = k-stride)
//   TA=true : A source [k][m] (lda = m-stride), loaded via trans ldmatrix
//   I2C     : B built on-the-fly from im2col of Bm (3x3 SAME conv)
// ===========================================================================
template <int EPI, bool TA, bool I2C>
__global__ __launch_bounds__(256, 1) void k_mm(
    const float* __restrict__ A, size_t Abs, int lda,
    const float* __restrict__ Bm, size_t Bbs, int ldb, int Ktot,
    float* __restrict__ D, size_t Dbs, int ldd,
    const float* __restrict__ bias,
    const float* __restrict__ Res, size_t Rbs,
    const float* __restrict__ bns, const float* __restrict__ bnb,
    const float* __restrict__ bnm, const float* __restrict__ bnv)
{
    extern __shared__ char sm[];
    constexpr int ASZ = TA ? (BKT * N_PAD * 2) : (BMT * AK_PAD * 2);
    constexpr int BSZ = BKT * N_PAD * 2;
    constexpr int STG = 2 * ASZ + 2 * BSZ;

    const int tid = threadIdx.x, wid = tid >> 5, lane = tid & 31;
    const int wm = wid & 3, wn = wid >> 2;
    const int colT = blockIdx.x * BNT, rowT = blockIdx.y * BMT, bz = blockIdx.z;
    const uint32_t su = smem_u32(sm);

    const float* Ab = A  + (size_t)bz * Abs;
    const float* Bb = Bm + (size_t)bz * Bbs;

    float acc[2][8][4];
    #pragma unroll
    for (int i = 0; i < 2; i++)
        #pragma unroll
        for (int j = 0; j < 8; j++)
            #pragma unroll
            for (int q = 0; q < 4; q++) acc[i][j][q] = 0.f;

    // ---- staging regs ----
    float4 stA[4];
    float4 stB[4];
    float  stC[16];

    // ---- loaders ----
    auto ldA = [&](int k0) {
        #pragma unroll
        for (int i = 0; i < 4; i++) {
            const int idx = tid + (i << 8);
            if constexpr (!TA) {
                stA[i] = *(const float4*)(Ab + (size_t)(rowT + (idx >> 3)) * lda
                                          + k0 + ((idx & 7) << 2));
            } else {
                stA[i] = *(const float4*)(Ab + (size_t)(k0 + (idx >> 5)) * lda
                                          + rowT + ((idx & 31) << 2));
            }
        }
    };
    auto stsA = [&](int s) {
        char* hi = sm + s * STG;
        char* lo = hi + ASZ;
        #pragma unroll
        for (int i = 0; i < 4; i++) {
            const int idx = tid + (i << 8);
            uint32_t off;
            if constexpr (!TA)
                off = (uint32_t)(idx >> 3) * (AK_PAD * 2) + ((idx & 7) << 3);
            else
                off = (uint32_t)(idx >> 5) * (N_PAD * 2) + ((idx & 31) << 3);
            cvt_sts4(hi, lo, off, stA[i]);
        }
    };
    auto ldB = [&](int k0) {
        if constexpr (!I2C) {
            #pragma unroll
            for (int i = 0; i < 4; i++) {
                const int idx = tid + (i << 8);
                stB[i] = *(const float4*)(Bb + (size_t)(k0 + (idx >> 5)) * ldb
                                          + colT + ((idx & 31) << 2));
            }
        } else {
            #pragma unroll
            for (int j = 0; j < 4; j++) {
                const int kg = k0 + (tid >> 5) + j * 8;
                const int c  = kg / 9;
                const int r  = kg - c * 9;
                const int ky = r / 3;
                const int kx = r - ky * 3;
                const float* src = Bb + (size_t)c * NPIX;
                #pragma unroll
                for (int u = 0; u < 4; u++) {
                    const int p = colT + ((tid & 31) << 2) + u;
                    const int y = p / WWW, x = p - y * WWW;
                    const int sy = y + ky - 1, sx = x + kx - 1;
                    stC[j * 4 + u] =
                        ((unsigned)sy < (unsigned)HHH && (unsigned)sx < (unsigned)WWW)
                            ? src[sy * WWW + sx] : 0.f;
                }
            }
        }
    };
    auto stsB = [&](int s) {
        char* hi = sm + s * STG + 2 * ASZ;
        char* lo = hi + BSZ;
        if constexpr (!I2C) {
            #pragma unroll
            for (int i = 0; i < 4; i++) {
                const int idx = tid + (i << 8);
                uint32_t off = (uint32_t)(idx >> 5) * (N_PAD * 2) + ((idx & 31) << 3);
                cvt_sts4(hi, lo, off, stB[i]);
            }
        } else {
            #pragma unroll
            for (int j = 0; j < 4; j++) {
                uint32_t off = (uint32_t)((tid >> 5) + j * 8) * (N_PAD * 2)
                               + ((tid & 31) << 3);
                float4 v = make_float4(stC[j*4], stC[j*4+1], stC[j*4+2], stC[j*4+3]);
                cvt_sts4(hi, lo, off, v);
            }
        }
    };

    // ---- ldmatrix address components (constant per thread) ----
    const int mtx = lane >> 3, r8 = lane & 7;
    // A offsets for (mi, ks)
    uint32_t aoff[2][2];
    #pragma unroll
    for (int mi = 0; mi < 2; mi++)
        #pragma unroll
        for (int ks = 0; ks < 2; ks++) {
            if constexpr (!TA) {
                const int row = wm * 32 + mi * 16 + (mtx & 1) * 8 + r8;
                const int kc  = ks * 16 + (mtx >> 1) * 8;
                aoff[mi][ks] = (uint32_t)row * (AK_PAD * 2) + kc * 2;
            } else {
                const int kk = ks * 16 + (mtx >> 1) * 8 + r8;
                const int mm = wm * 32 + mi * 16 + (mtx & 1) * 8;
                aoff[mi][ks] = (uint32_t)kk * (N_PAD * 2) + mm * 2;
            }
        }
    // B offsets for (ni2, ks)
    uint32_t boff[4][2];
    #pragma unroll
    for (int ni2 = 0; ni2 < 4; ni2++)
        #pragma unroll
        for (int ks = 0; ks < 2; ks++) {
            const int kb = ks * 16 + (mtx & 1) * 8 + r8;
            const int nb = wn * 64 + ni2 * 16 + (mtx >> 1) * 8;
            boff[ni2][ks] = (uint32_t)kb * (N_PAD * 2) + nb * 2;
        }

    // ---- mainloop ----
    ldA(0); ldB(0);
    stsA(0); stsB(0);
    __syncthreads();

    const int nch = Ktot / BKT;
    for (int i = 0; i < nch; i++) {
        const int s = i & 1;
        if (i + 1 < nch) { ldA((i + 1) * BKT); ldB((i + 1) * BKT); }

        const uint32_t aHi = su + s * STG;
        const uint32_t aLo = aHi + ASZ;
        const uint32_t bHi = su + s * STG + 2 * ASZ;
        const uint32_t bLo = bHi + BSZ;

        #pragma unroll
        for (int ks = 0; ks < 2; ks++) {
            uint32_t ah[2][4], al[2][4];
            #pragma unroll
            for (int mi = 0; mi < 2; mi++) {
                if constexpr (!TA) {
                    LDMX4(ah[mi], aHi + aoff[mi][ks]);
                    LDMX4(al[mi], aLo + aoff[mi][ks]);
                } else {
                    LDMX4T(ah[mi], aHi + aoff[mi][ks]);
                    LDMX4T(al[mi], aLo + aoff[mi][ks]);
                }
            }
            #pragma unroll
            for (int ni2 = 0; ni2 < 4; ni2++) {
                uint32_t bh[4], bl[4];
                LDMX4T(bh, bHi + boff[ni2][ks]);
                LDMX4T(bl, bLo + boff[ni2][ks]);
                #pragma unroll
                for (int mi = 0; mi < 2; mi++) {
                    #pragma unroll
                    for (int nf = 0; nf < 2; nf++) {
                        float* ac = acc[mi][ni2 * 2 + nf];
                        MMA16816(ac, ah[mi], bh + nf * 2);
                        MMA16816(ac, ah[mi], bl + nf * 2);
                        MMA16816(ac, al[mi], bh + nf * 2);
                    }
                }
            }
        }
        if (i + 1 < nch) { stsA(s ^ 1); stsB(s ^ 1); }
        __syncthreads();
    }

    // ---- epilogue ----
    #pragma unroll
    for (int mi = 0; mi < 2; mi++) {
        const int r = rowT + wm * 32 + mi * 16 + (lane >> 2);
        float ba = 0.f, bb_ = 0.f, inva = 0.f, beta_a = 0.f, invb = 0.f, beta_b = 0.f;
        if (EPI == E_BROW) { ba = bias[r]; bb_ = bias[r + 8]; }
        if (EPI == E_BN || EPI == E_BNRES) {
            inva = bns[r] * rsqrtf(bnv[r] + EPSB);
            beta_a = bnb[r] - bnm[r] * inva;
            invb = bns[r + 8] * rsqrtf(bnv[r + 8] + EPSB);
            beta_b = bnb[r + 8] - bnm[r + 8] * invb;
        }
        float* d0 = D + (size_t)bz * Dbs + (size_t)r * ldd;
        float* d1 = d0 + 8 * (size_t)ldd;
        const float* rs0 = (EPI == E_RES || EPI == E_BNRES)
                               ? Res + (size_t)bz * Rbs + (size_t)r * ldd : nullptr;
        const float* rs1 = rs0 ? rs0 + 8 * (size_t)ldd : nullptr;
        #pragma unroll
        for (int ni = 0; ni < 8; ni++) {
            const int c = colT + wn * 64 + ni * 8 + ((lane & 3) << 1);
            float v0 = acc[mi][ni][0], v1 = acc[mi][ni][1];
            float v2 = acc[mi][ni][2], v3 = acc[mi][ni][3];
            if (EPI == E_BROW) {
                v0 += ba; v1 += ba; v2 += bb_; v3 += bb_;
            } else if (EPI == E_RES) {
                float2 f0 = *(const float2*)(rs0 + c);
                float2 f1 = *(const float2*)(rs1 + c);
                v0 += f0.x; v1 += f0.y; v2 += f1.x; v3 += f1.y;
            } else if (EPI == E_BN) {
                v0 = fmaxf(v0 * inva + beta_a, 0.f);
                v1 = fmaxf(v1 * inva + beta_a, 0.f);
                v2 = fmaxf(v2 * invb + beta_b, 0.f);
                v3 = fmaxf(v3 * invb + beta_b, 0.f);
            } else if (EPI == E_BNRES) {
                float2 f0 = *(const float2*)(rs0 + c);
                float2 f1 = *(const float2*)(rs1 + c);
                v0 = fmaxf(v0 * inva + beta_a + f0.x, 0.f) + f0.x;
                v1 = fmaxf(v1 * inva + beta_a + f0.y, 0.f) + f0.y;
                v2 = fmaxf(v2 * invb + beta_b + f1.x, 0.f) + f1.x;
                v3 = fmaxf(v3 * invb + beta_b + f1.y, 0.f) + f1.y;
            }
            *(float2*)(d0 + c) = make_float2(v0, v1);
            *(float2*)(d1 + c) = make_float2(v2, v3);
        }
    }
}

// ===========================================================================
// Row softmax over last axis (rows of length NPIX), in place (from R2)
// ===========================================================================
__global__ __launch_bounds__(256) void k_softmax(float* __restrict__ A)
{
    float* p = A + (size_t)blockIdx.x * NPIX;
    const int tid = threadIdx.x;
    float v[9];
    float mx = -1e30f;
    #pragma unroll
    for (int i = 0; i < 9; i++) {
        v[i] = p[tid + (i << 8)];
        mx = fmaxf(mx, v[i]);
    }
    __shared__ float red[8];
    #pragma unroll
    for (int o = 16; o > 0; o >>= 1)
        mx = fmaxf(mx, __shfl_xor_sync(0xffffffffu, mx, o));
    if ((tid & 31) == 0) red[tid >> 5] = mx;
    __syncthreads();
    float m2 = red[0];
    #pragma unroll
    for (int i = 1; i < 8; i++) m2 = fmaxf(m2, red[i]);
    __syncthreads();
    float s = 0.f;
    #pragma unroll
    for (int i = 0; i < 9; i++) { v[i] = __expf(v[i] - m2); s += v[i]; }
    #pragma unroll
    for (int o = 16; o > 0; o >>= 1)
        s += __shfl_xor_sync(0xffffffffu, s, o);
    if ((tid & 31) == 0) red[tid >> 5] = s;
    __syncthreads();
    float s2 = 0.f;
    #pragma unroll
    for (int i = 0; i < 8; i++) s2 += red[i];
    const float inv = 1.0f / s2;
    #pragma unroll
    for (int i = 0; i < 9; i++) p[tid + (i << 8)] = v[i] * inv;
}

// ===========================================================================
// Host launcher
// ===========================================================================
extern "C" void kernel_launch(void* const* d_in, const int* in_sizes, int n_in,
                              void* d_out, int out_size)
{
    (void)in_sizes; (void)n_in; (void)out_size;
    const float* F_b  = (const float*)d_in[0];
    const float* F_a  = (const float*)d_in[1];
    const float* qw   = (const float*)d_in[2];
    const float* qb   = (const float*)d_in[3];
    const float* kw   = (const float*)d_in[4];
    const float* kb   = (const float*)d_in[5];
    const float* vw   = (const float*)d_in[6];
    const float* vb   = (const float*)d_in[7];
    const float* c1w  = (const float*)d_in[8];
    const float* bn1s = (const float*)d_in[9];
    const float* bn1b = (const float*)d_in[10];
    const float* bn1m = (const float*)d_in[11];
    const float* bn1v = (const float*)d_in[12];
    const float* c2w  = (const float*)d_in[13];
    const float* bn2s = (const float*)d_in[14];
    const float* bn2b = (const float*)d_in[15];
    const float* bn2m = (const float*)d_in[16];
    const float* bn2v = (const float*)d_in[17];
    float* out = (float*)d_out;

    float *Q, *K, *V, *fused, *tmp, *attn;
    cudaGetSymbolAddress((void**)&Q,     g_Q);
    cudaGetSymbolAddress((void**)&K,     g_K);
    cudaGetSymbolAddress((void**)&V,     g_V);
    cudaGetSymbolAddress((void**)&fused, g_fused);
    cudaGetSymbolAddress((void**)&tmp,   g_tmp);
    cudaGetSymbolAddress((void**)&attn,  g_attn);

    // dynamic smem sizes
    const int SMEM_MK = 2 * (2 * BMT * AK_PAD * 2 + 2 * BKT * N_PAD * 2); // 75776
    const int SMEM_KM = 2 * (4 * BKT * N_PAD * 2);                        // 69632

    cudaFuncSetAttribute(k_mm<E_BROW,  false, false>, cudaFuncAttributeMaxDynamicSharedMemorySize, SMEM_MK);
    cudaFuncSetAttribute(k_mm<E_NONE,  true,  false>, cudaFuncAttributeMaxDynamicSharedMemorySize, SMEM_KM);
    cudaFuncSetAttribute(k_mm<E_RES,   false, false>, cudaFuncAttributeMaxDynamicSharedMemorySize, SMEM_MK);
    cudaFuncSetAttribute(k_mm<E_BN,    false, true >, cudaFuncAttributeMaxDynamicSharedMemorySize, SMEM_MK);
    cudaFuncSetAttribute(k_mm<E_BNRES, false, true >, cudaFuncAttributeMaxDynamicSharedMemorySize, SMEM_MK);

    dim3 blk(256);
    dim3 gFeat(NPIX / BNT, CCH / BMT, BBATCH);   // (18, 2, 16)
    dim3 gScor(NPIX / BNT, NPIX / BMT, BBATCH);  // (18, 18, 16)
    const size_t FS = (size_t)CCH * NPIX;        // feature map batch stride
    const size_t AS = (size_t)NPIX * NPIX;       // attn batch stride

    // Q = qw . F_b + qb ; K,V from F_a
    k_mm<E_BROW, false, false><<<gFeat, blk, SMEM_MK>>>(
        qw, 0, CCH, F_b, FS, NPIX, CCH, Q, FS, NPIX,
        qb, nullptr, 0, nullptr, nullptr, nullptr, nullptr);
    k_mm<E_BROW, false, false><<<gFeat, blk, SMEM_MK>>>(
        kw, 0, CCH, F_a, FS, NPIX, CCH, K, FS, NPIX,
        kb, nullptr, 0, nullptr, nullptr, nullptr, nullptr);
    k_mm<E_BROW, false, false><<<gFeat, blk, SMEM_MK>>>(
        vw, 0, CCH, F_a, FS, NPIX, CCH, V, FS, NPIX,
        vb, nullptr, 0, nullptr, nullptr, nullptr, nullptr);

    // scores[n][m] = sum_c K[c][n] * Q[c][m]   (A = K via trans path)
    k_mm<E_NONE, true, false><<<gScor, blk, SMEM_KM>>>(
        K, FS, NPIX, Q, FS, NPIX, CCH, attn, AS, NPIX,
        nullptr, nullptr, 0, nullptr, nullptr, nullptr, nullptr);

    // softmax over m (rows of attn)
    k_softmax<<<BBATCH * NPIX, 256>>>(attn);

    // fused[c][m] = sum_n V[c][n] * attn[n][m] + F_b
    k_mm<E_RES, false, false><<<gFeat, blk, SMEM_MK>>>(
        V, FS, NPIX, attn, AS, NPIX, NPIX, fused, FS, NPIX,
        nullptr, F_b, FS, nullptr, nullptr, nullptr, nullptr);

    // conv1 + bn1 + relu -> tmp
    k_mm<E_BN, false, true><<<gFeat, blk, SMEM_MK>>>(
        c1w, 0, KCONV, fused, FS, 0, KCONV, tmp, FS, NPIX,
        nullptr, nullptr, 0, bn1s, bn1b, bn1m, bn1v);
    // conv2 + bn2 + residual(fused) -> out
    k_mm<E_BNRES, false, true><<<gFeat, blk, SMEM_MK>>>(
        c2w, 0, KCONV, tmp, FS, 0, KCONV, out, FS, NPIX,
        nullptr, fused, FS, bn2s, bn2b, bn2m, bn2v);
}

// round 7
// speedup vs baseline: 2.4938x; 1.1459x over previous
#include <cuda_runtime.h>
#include <cuda_bf16.h>
#include <cstdint>

#define BBATCH 16
#define CCH    256
#define HHH    48
#define WWW    48
#define NPIX   2304
#define KCONV  2304
#define EPSB   1e-5f

#define BMT 128
#define BNT 64
#define BKT 32

#define AK_PAD 40     // A [m][k] rows: 40 bf16 = 80B
#define AM_PAD 136    // A [k][m] rows (TA): 136 bf16 = 272B
#define BN_PAD 72     // B [k][n] rows: 72 bf16 = 144B

// ---------------- scratch ----------------
__device__ float g_Q    [(size_t)BBATCH * CCH * NPIX];
__device__ float g_K    [(size_t)BBATCH * CCH * NPIX];
__device__ float g_V    [(size_t)BBATCH * CCH * NPIX];
__device__ float g_fused[(size_t)BBATCH * CCH * NPIX];
__device__ float g_tmp  [(size_t)BBATCH * CCH * NPIX];
__device__ float g_attn [(size_t)BBATCH * NPIX * NPIX];

// ---------------- helpers ----------------
__device__ __forceinline__ uint32_t smem_u32(const void* p) {
    uint32_t a;
    asm("{ .reg .u64 t; cvta.to.shared.u64 t, %1; cvt.u32.u64 %0, t; }"
        : "=r"(a) : "l"(p));
    return a;
}
__device__ __forceinline__ uint32_t pk(__nv_bfloat16 a, __nv_bfloat16 b) {
    return (uint32_t)__bfloat16_as_ushort(a) |
           ((uint32_t)__bfloat16_as_ushort(b) << 16);
}
__device__ __forceinline__ void spl(float x, __nv_bfloat16& h, __nv_bfloat16& l) {
    h = __float2bfloat16(x);
    l = __float2bfloat16(x - __bfloat162float(h));
}
__device__ __forceinline__ void cvt_sts4(char* hi, char* lo, uint32_t off, float4 v) {
    __nv_bfloat16 h0,l0,h1,l1,h2,l2,h3,l3;
    spl(v.x,h0,l0); spl(v.y,h1,l1); spl(v.z,h2,l2); spl(v.w,h3,l3);
    *(uint2*)(hi + off) = make_uint2(pk(h0,h1), pk(h2,h3));
    *(uint2*)(lo + off) = make_uint2(pk(l0,l1), pk(l2,l3));
}

#define LDMX4(R, addr) \
    asm volatile("ldmatrix.sync.aligned.m8n8.x4.shared.b16 {%0,%1,%2,%3}, [%4];" \
        : "=r"((R)[0]), "=r"((R)[1]), "=r"((R)[2]), "=r"((R)[3]) : "r"(addr))
#define LDMX4T(R, addr) \
    asm volatile("ldmatrix.sync.aligned.m8n8.x4.trans.shared.b16 {%0,%1,%2,%3}, [%4];" \
        : "=r"((R)[0]), "=r"((R)[1]), "=r"((R)[2]), "=r"((R)[3]) : "r"(addr))
#define MMA16816(d, a, b) \
    asm volatile("mma.sync.aligned.m16n8k16.row.col.f32.bf16.bf16.f32 " \
        "{%0,%1,%2,%3}, {%4,%5,%6,%7}, {%8,%9}, {%0,%1,%2,%3};" \
        : "+f"((d)[0]), "+f"((d)[1]), "+f"((d)[2]), "+f"((d)[3]) \
        : "r"((a)[0]), "r"((a)[1]), "r"((a)[2]), "r"((a)[3]), \
          "r"((b)[0]), "r"((b)[1]))

enum { E_NONE = 0, E_BROW = 1, E_RES = 2, E_BN = 3, E_BNRES = 4 };

// ===========================================================================
// HMMA GEMM: D[m][n] = sum_k A[m][k]*B[k][n]; tile 128x64x32, 8 warps (4x2),
// warp tile 32x32, 2 CTAs/SM.
// ===========================================================================
template <int EPI, bool TA, bool I2C>
__global__ __launch_bounds__(256, 2) void k_mm(
    const float* __restrict__ A, size_t Abs, int lda,
    const float* __restrict__ Bm, size_t Bbs, int ldb, int Ktot,
    float* __restrict__ D, size_t Dbs, int ldd,
    const float* __restrict__ bias,
    const float* __restrict__ Res, size_t Rbs,
    const float* __restrict__ bns, const float* __restrict__ bnb,
    const float* __restrict__ bnm, const float* __restrict__ bnv)
{
    extern __shared__ char sm[];
    constexpr int ASZ = TA ? (BKT * AM_PAD * 2) : (BMT * AK_PAD * 2);
    constexpr int BSZ = BKT * BN_PAD * 2;
    constexpr int STG = 2 * ASZ + 2 * BSZ;

    const int tid = threadIdx.x, wid = tid >> 5, lane = tid & 31;
    const int wm = wid & 3, wn = wid >> 2;          // 4 x 2 warp grid
    const int colT = blockIdx.x * BNT, rowT = blockIdx.y * BMT, bz = blockIdx.z;
    const uint32_t su = smem_u32(sm);

    const float* Ab = A  + (size_t)bz * Abs;
    const float* Bb = Bm + (size_t)bz * Bbs;

    float acc[2][4][4];
    #pragma unroll
    for (int i = 0; i < 2; i++)
        #pragma unroll
        for (int j = 0; j < 4; j++)
            #pragma unroll
            for (int q = 0; q < 4; q++) acc[i][j][q] = 0.f;

    float4 stA[4];
    float4 stB[2];
    float  stC[8];

    auto ldA = [&](int k0) {
        #pragma unroll
        for (int i = 0; i < 4; i++) {
            const int idx = tid + (i << 8);
            if constexpr (!TA)
                stA[i] = *(const float4*)(Ab + (size_t)(rowT + (idx >> 3)) * lda
                                          + k0 + ((idx & 7) << 2));
            else
                stA[i] = *(const float4*)(Ab + (size_t)(k0 + (idx >> 5)) * lda
                                          + rowT + ((idx & 31) << 2));
        }
    };
    auto stsA = [&](int s) {
        char* hi = sm + s * STG;
        char* lo = hi + ASZ;
        #pragma unroll
        for (int i = 0; i < 4; i++) {
            const int idx = tid + (i << 8);
            uint32_t off;
            if constexpr (!TA)
                off = (uint32_t)(idx >> 3) * (AK_PAD * 2) + ((idx & 7) << 3);
            else
                off = (uint32_t)(idx >> 5) * (AM_PAD * 2) + ((idx & 31) << 3);
            cvt_sts4(hi, lo, off, stA[i]);
        }
    };
    auto ldB = [&](int k0) {
        if constexpr (!I2C) {
            #pragma unroll
            for (int i = 0; i < 2; i++) {
                const int idx = tid + (i << 8);
                stB[i] = *(const float4*)(Bb + (size_t)(k0 + (idx >> 4)) * ldb
                                          + colT + ((idx & 15) << 2));
            }
        } else {
            #pragma unroll
            for (int j = 0; j < 2; j++) {
                const int kg = k0 + (tid >> 4) + j * 16;
                const int c  = kg / 9;
                const int r  = kg - c * 9;
                const int ky = r / 3;
                const int kx = r - ky * 3;
                const float* src = Bb + (size_t)c * NPIX;
                #pragma unroll
                for (int u = 0; u < 4; u++) {
                    const int p = colT + ((tid & 15) << 2) + u;
                    const int y = p / WWW, x = p - y * WWW;
                    const int sy = y + ky - 1, sx = x + kx - 1;
                    stC[j * 4 + u] =
                        ((unsigned)sy < (unsigned)HHH && (unsigned)sx < (unsigned)WWW)
                            ? src[sy * WWW + sx] : 0.f;
                }
            }
        }
    };
    auto stsB = [&](int s) {
        char* hi = sm + s * STG + 2 * ASZ;
        char* lo = hi + BSZ;
        if constexpr (!I2C) {
            #pragma unroll
            for (int i = 0; i < 2; i++) {
                const int idx = tid + (i << 8);
                uint32_t off = (uint32_t)(idx >> 4) * (BN_PAD * 2) + ((idx & 15) << 3);
                cvt_sts4(hi, lo, off, stB[i]);
            }
        } else {
            #pragma unroll
            for (int j = 0; j < 2; j++) {
                uint32_t off = (uint32_t)((tid >> 4) + j * 16) * (BN_PAD * 2)
                               + ((tid & 15) << 3);
                float4 v = make_float4(stC[j*4], stC[j*4+1], stC[j*4+2], stC[j*4+3]);
                cvt_sts4(hi, lo, off, v);
            }
        }
    };

    const int mtx = lane >> 3, r8 = lane & 7;
    uint32_t aoff[2][2];
    #pragma unroll
    for (int mi = 0; mi < 2; mi++)
        #pragma unroll
        for (int ks = 0; ks < 2; ks++) {
            if constexpr (!TA) {
                const int row = wm * 32 + mi * 16 + (mtx & 1) * 8 + r8;
                const int kc  = ks * 16 + (mtx >> 1) * 8;
                aoff[mi][ks] = (uint32_t)row * (AK_PAD * 2) + kc * 2;
            } else {
                const int kk = ks * 16 + (mtx >> 1) * 8 + r8;
                const int mm = wm * 32 + mi * 16 + (mtx & 1) * 8;
                aoff[mi][ks] = (uint32_t)kk * (AM_PAD * 2) + mm * 2;
            }
        }
    uint32_t boff[2][2];
    #pragma unroll
    for (int ni2 = 0; ni2 < 2; ni2++)
        #pragma unroll
        for (int ks = 0; ks < 2; ks++) {
            const int kb = ks * 16 + (mtx & 1) * 8 + r8;
            const int nb = wn * 32 + ni2 * 16 + (mtx >> 1) * 8;
            boff[ni2][ks] = (uint32_t)kb * (BN_PAD * 2) + nb * 2;
        }

    ldA(0); ldB(0);
    stsA(0); stsB(0);
    __syncthreads();

    const int nch = Ktot / BKT;
    for (int i = 0; i < nch; i++) {
        const int s = i & 1;
        if (i + 1 < nch) { ldA((i + 1) * BKT); ldB((i + 1) * BKT); }

        const uint32_t aHi = su + s * STG;
        const uint32_t aLo = aHi + ASZ;
        const uint32_t bHi = su + s * STG + 2 * ASZ;
        const uint32_t bLo = bHi + BSZ;

        #pragma unroll
        for (int ks = 0; ks < 2; ks++) {
            uint32_t ah[2][4], al[2][4];
            #pragma unroll
            for (int mi = 0; mi < 2; mi++) {
                if constexpr (!TA) {
                    LDMX4(ah[mi], aHi + aoff[mi][ks]);
                    LDMX4(al[mi], aLo + aoff[mi][ks]);
                } else {
                    LDMX4T(ah[mi], aHi + aoff[mi][ks]);
                    LDMX4T(al[mi], aLo + aoff[mi][ks]);
                }
            }
            #pragma unroll
            for (int ni2 = 0; ni2 < 2; ni2++) {
                uint32_t bh[4], bl[4];
                LDMX4T(bh, bHi + boff[ni2][ks]);
                LDMX4T(bl, bLo + boff[ni2][ks]);
                #pragma unroll
                for (int mi = 0; mi < 2; mi++) {
                    #pragma unroll
                    for (int nf = 0; nf < 2; nf++) {
                        float* ac = acc[mi][ni2 * 2 + nf];
                        MMA16816(ac, ah[mi], bh + nf * 2);
                        MMA16816(ac, ah[mi], bl + nf * 2);
                        MMA16816(ac, al[mi], bh + nf * 2);
                    }
                }
            }
        }
        if (i + 1 < nch) { stsA(s ^ 1); stsB(s ^ 1); }
        __syncthreads();
    }

    // ---- epilogue ----
    #pragma unroll
    for (int mi = 0; mi < 2; mi++) {
        const int r = rowT + wm * 32 + mi * 16 + (lane >> 2);
        float ba = 0.f, bb_ = 0.f, inva = 0.f, beta_a = 0.f, invb = 0.f, beta_b = 0.f;
        if (EPI == E_BROW) { ba = bias[r]; bb_ = bias[r + 8]; }
        if (EPI == E_BN || EPI == E_BNRES) {
            inva = bns[r] * rsqrtf(bnv[r] + EPSB);
            beta_a = bnb[r] - bnm[r] * inva;
            invb = bns[r + 8] * rsqrtf(bnv[r + 8] + EPSB);
            beta_b = bnb[r + 8] - bnm[r + 8] * invb;
        }
        float* d0 = D + (size_t)bz * Dbs + (size_t)r * ldd;
        float* d1 = d0 + 8 * (size_t)ldd;
        const float* rs0 = (EPI == E_RES || EPI == E_BNRES)
                               ? Res + (size_t)bz * Rbs + (size_t)r * ldd : nullptr;
        const float* rs1 = rs0 ? rs0 + 8 * (size_t)ldd : nullptr;
        #pragma unroll
        for (int ni = 0; ni < 4; ni++) {
            const int c = colT + wn * 32 + ni * 8 + ((lane & 3) << 1);
            float v0 = acc[mi][ni][0], v1 = acc[mi][ni][1];
            float v2 = acc[mi][ni][2], v3 = acc[mi][ni][3];
            if (EPI == E_BROW) {
                v0 += ba; v1 += ba; v2 += bb_; v3 += bb_;
            } else if (EPI == E_RES) {
                float2 f0 = *(const float2*)(rs0 + c);
                float2 f1 = *(const float2*)(rs1 + c);
                v0 += f0.x; v1 += f0.y; v2 += f1.x; v3 += f1.y;
            } else if (EPI == E_BN) {
                v0 = fmaxf(v0 * inva + beta_a, 0.f);
                v1 = fmaxf(v1 * inva + beta_a, 0.f);
                v2 = fmaxf(v2 * invb + beta_b, 0.f);
                v3 = fmaxf(v3 * invb + beta_b, 0.f);
            } else if (EPI == E_BNRES) {
                float2 f0 = *(const float2*)(rs0 + c);
                float2 f1 = *(const float2*)(rs1 + c);
                v0 = fmaxf(v0 * inva + beta_a + f0.x, 0.f) + f0.x;
                v1 = fmaxf(v1 * inva + beta_a + f0.y, 0.f) + f0.y;
                v2 = fmaxf(v2 * invb + beta_b + f1.x, 0.f) + f1.x;
                v3 = fmaxf(v3 * invb + beta_b + f1.y, 0.f) + f1.y;
            }
            *(float2*)(d0 + c) = make_float2(v0, v1);
            *(float2*)(d1 + c) = make_float2(v2, v3);
        }
    }
}

// ===========================================================================
// Row softmax (rows of length NPIX), in place
// ===========================================================================
__global__ __launch_bounds__(256) void k_softmax(float* __restrict__ A)
{
    float* p = A + (size_t)blockIdx.x * NPIX;
    const int tid = threadIdx.x;
    float v[9];
    float mx = -1e30f;
    #pragma unroll
    for (int i = 0; i < 9; i++) {
        v[i] = p[tid + (i << 8)];
        mx = fmaxf(mx, v[i]);
    }
    __shared__ float red[8];
    #pragma unroll
    for (int o = 16; o > 0; o >>= 1)
        mx = fmaxf(mx, __shfl_xor_sync(0xffffffffu, mx, o));
    if ((tid & 31) == 0) red[tid >> 5] = mx;
    __syncthreads();
    float m2 = red[0];
    #pragma unroll
    for (int i = 1; i < 8; i++) m2 = fmaxf(m2, red[i]);
    __syncthreads();
    float s = 0.f;
    #pragma unroll
    for (int i = 0; i < 9; i++) { v[i] = __expf(v[i] - m2); s += v[i]; }
    #pragma unroll
    for (int o = 16; o > 0; o >>= 1)
        s += __shfl_xor_sync(0xffffffffu, s, o);
    if ((tid & 31) == 0) red[tid >> 5] = s;
    __syncthreads();
    float s2 = 0.f;
    #pragma unroll
    for (int i = 0; i < 8; i++) s2 += red[i];
    const float inv = 1.0f / s2;
    #pragma unroll
    for (int i = 0; i < 9; i++) p[tid + (i << 8)] = v[i] * inv;
}

// ===========================================================================
// Host launcher
// ===========================================================================
extern "C" void kernel_launch(void* const* d_in, const int* in_sizes, int n_in,
                              void* d_out, int out_size)
{
    (void)in_sizes; (void)n_in; (void)out_size;
    const float* F_b  = (const float*)d_in[0];
    const float* F_a  = (const float*)d_in[1];
    const float* qw   = (const float*)d_in[2];
    const float* qb   = (const float*)d_in[3];
    const float* kw   = (const float*)d_in[4];
    const float* kb   = (const float*)d_in[5];
    const float* vw   = (const float*)d_in[6];
    const float* vb   = (const float*)d_in[7];
    const float* c1w  = (const float*)d_in[8];
    const float* bn1s = (const float*)d_in[9];
    const float* bn1b = (const float*)d_in[10];
    const float* bn1m = (const float*)d_in[11];
    const float* bn1v = (const float*)d_in[12];
    const float* c2w  = (const float*)d_in[13];
    const float* bn2s = (const float*)d_in[14];
    const float* bn2b = (const float*)d_in[15];
    const float* bn2m = (const float*)d_in[16];
    const float* bn2v = (const float*)d_in[17];
    float* out = (float*)d_out;

    float *Q, *K, *V, *fused, *tmp, *attn;
    cudaGetSymbolAddress((void**)&Q,     g_Q);
    cudaGetSymbolAddress((void**)&K,     g_K);
    cudaGetSymbolAddress((void**)&V,     g_V);
    cudaGetSymbolAddress((void**)&fused, g_fused);
    cudaGetSymbolAddress((void**)&tmp,   g_tmp);
    cudaGetSymbolAddress((void**)&attn,  g_attn);

    const int SMEM_MK = 2 * (2 * BMT * AK_PAD * 2 + 2 * BKT * BN_PAD * 2); // 59392
    const int SMEM_KM = 2 * (2 * BKT * AM_PAD * 2 + 2 * BKT * BN_PAD * 2); // 53248

    cudaFuncSetAttribute(k_mm<E_BROW,  false, false>, cudaFuncAttributeMaxDynamicSharedMemorySize, SMEM_MK);
    cudaFuncSetAttribute(k_mm<E_NONE,  true,  false>, cudaFuncAttributeMaxDynamicSharedMemorySize, SMEM_KM);
    cudaFuncSetAttribute(k_mm<E_RES,   false, false>, cudaFuncAttributeMaxDynamicSharedMemorySize, SMEM_MK);
    cudaFuncSetAttribute(k_mm<E_BN,    false, true >, cudaFuncAttributeMaxDynamicSharedMemorySize, SMEM_MK);
    cudaFuncSetAttribute(k_mm<E_BNRES, false, true >, cudaFuncAttributeMaxDynamicSharedMemorySize, SMEM_MK);

    dim3 blk(256);
    dim3 gFeat(NPIX / BNT, CCH / BMT, BBATCH);   // (36, 2, 16)
    dim3 gScor(NPIX / BNT, NPIX / BMT, BBATCH);  // (36, 18, 16)
    const size_t FS = (size_t)CCH * NPIX;
    const size_t AS = (size_t)NPIX * NPIX;

    k_mm<E_BROW, false, false><<<gFeat, blk, SMEM_MK>>>(
        qw, 0, CCH, F_b, FS, NPIX, CCH, Q, FS, NPIX,
        qb, nullptr, 0, nullptr, nullptr, nullptr, nullptr);
    k_mm<E_BROW, false, false><<<gFeat, blk, SMEM_MK>>>(
        kw, 0, CCH, F_a, FS, NPIX, CCH, K, FS, NPIX,
        kb, nullptr, 0, nullptr, nullptr, nullptr, nullptr);
    k_mm<E_BROW, false, false><<<gFeat, blk, SMEM_MK>>>(
        vw, 0, CCH, F_a, FS, NPIX, CCH, V, FS, NPIX,
        vb, nullptr, 0, nullptr, nullptr, nullptr, nullptr);

    // scores[n][m] = sum_c K[c][n] * Q[c][m]
    k_mm<E_NONE, true, false><<<gScor, blk, SMEM_KM>>>(
        K, FS, NPIX, Q, FS, NPIX, CCH, attn, AS, NPIX,
        nullptr, nullptr, 0, nullptr, nullptr, nullptr, nullptr);

    k_softmax<<<BBATCH * NPIX, 256>>>(attn);

    // fused = V @ attn + F_b
    k_mm<E_RES, false, false><<<gFeat, blk, SMEM_MK>>>(
        V, FS, NPIX, attn, AS, NPIX, NPIX, fused, FS, NPIX,
        nullptr, F_b, FS, nullptr, nullptr, nullptr, nullptr);

    k_mm<E_BN, false, true><<<gFeat, blk, SMEM_MK>>>(
        c1w, 0, KCONV, fused, FS, 0, KCONV, tmp, FS, NPIX,
        nullptr, nullptr, 0, bn1s, bn1b, bn1m, bn1v);
    k_mm<E_BNRES, false, true><<<gFeat, blk, SMEM_MK>>>(
        c2w, 0, KCONV, tmp, FS, 0, KCONV, out, FS, NPIX,
        nullptr, fused, FS, bn2s, bn2b, bn2m, bn2v);
}

// round 8
// speedup vs baseline: 2.6154x; 1.0488x over previous
#include <cuda_runtime.h>
#include <cuda_bf16.h>
#include <cstdint>

#define BBATCH 16
#define CCH    256
#define HHH    48
#define WWW    48
#define NPIX   2304
#define KCONV  2304
#define EPSB   1e-5f

#define BMT 128
#define BNT 64
#define BKT 32

#define AK_PAD 40     // A [m][k] rows: 40 bf16 = 80B
#define AM_PAD 136    // A [k][m] rows (TA): 272B
#define BN_PAD 72     // B [k][n] rows: 144B

typedef __nv_bfloat16 bf16;

// ---------------- scratch ----------------
#define FSZ  ((size_t)BBATCH * CCH * NPIX)
#define ASZG ((size_t)BBATCH * NPIX * NPIX)

__device__ float g_scores[ASZG];
__device__ float g_fused [FSZ];

__device__ __align__(16) bf16 g_Fbh[FSZ], g_Fbl[FSZ], g_Fah[FSZ], g_Fal[FSZ];
__device__ __align__(16) bf16 g_qwh[CCH*CCH], g_qwl[CCH*CCH];
__device__ __align__(16) bf16 g_kwh[CCH*CCH], g_kwl[CCH*CCH];
__device__ __align__(16) bf16 g_vwh[CCH*CCH], g_vwl[CCH*CCH];
__device__ __align__(16) bf16 g_c1h[CCH*KCONV], g_c1l[CCH*KCONV];
__device__ __align__(16) bf16 g_c2h[CCH*KCONV], g_c2l[CCH*KCONV];
__device__ __align__(16) bf16 g_Qh[FSZ], g_Ql[FSZ], g_Kh[FSZ], g_Kl[FSZ];
__device__ __align__(16) bf16 g_Vh[FSZ], g_Vl[FSZ];
__device__ __align__(16) bf16 g_Ath[ASZG], g_Atl[ASZG];
__device__ __align__(16) bf16 g_Fh[FSZ], g_Fl[FSZ];
__device__ __align__(16) bf16 g_th[FSZ], g_tl[FSZ];

// ---------------- helpers ----------------
__device__ __forceinline__ uint32_t smem_u32(const void* p) {
    uint32_t a;
    asm("{ .reg .u64 t; cvta.to.shared.u64 t, %1; cvt.u32.u64 %0, t; }"
        : "=r"(a) : "l"(p));
    return a;
}
__device__ __forceinline__ uint32_t pk(bf16 a, bf16 b) {
    return (uint32_t)__bfloat16_as_ushort(a) |
           ((uint32_t)__bfloat16_as_ushort(b) << 16);
}
__device__ __forceinline__ void spl(float x, bf16& h, bf16& l) {
    h = __float2bfloat16(x);
    l = __float2bfloat16(x - __bfloat162float(h));
}
__device__ __forceinline__ void wr_bf(bf16* H, bf16* L, size_t off,
                                      float a, float b) {
    bf16 h0, l0, h1, l1;
    spl(a, h0, l0); spl(b, h1, l1);
    *(uint32_t*)(H + off) = pk(h0, h1);
    *(uint32_t*)(L + off) = pk(l0, l1);
}

#define CPA(d, s)     asm volatile("cp.async.cg.shared.global [%0], [%1], 16;" :: "r"(d), "l"(s))
#define CPA_COMMIT()  asm volatile("cp.async.commit_group;")
#define CPA_WAIT0()   asm volatile("cp.async.wait_group 0;")

#define LDMX4(R, addr) \
    asm volatile("ldmatrix.sync.aligned.m8n8.x4.shared.b16 {%0,%1,%2,%3}, [%4];" \
        : "=r"((R)[0]), "=r"((R)[1]), "=r"((R)[2]), "=r"((R)[3]) : "r"(addr))
#define LDMX4T(R, addr) \
    asm volatile("ldmatrix.sync.aligned.m8n8.x4.trans.shared.b16 {%0,%1,%2,%3}, [%4];" \
        : "=r"((R)[0]), "=r"((R)[1]), "=r"((R)[2]), "=r"((R)[3]) : "r"(addr))
#define MMA16816(d, a, b) \
    asm volatile("mma.sync.aligned.m16n8k16.row.col.f32.bf16.bf16.f32 " \
        "{%0,%1,%2,%3}, {%4,%5,%6,%7}, {%8,%9}, {%0,%1,%2,%3};" \
        : "+f"((d)[0]), "+f"((d)[1]), "+f"((d)[2]), "+f"((d)[3]) \
        : "r"((a)[0]), "r"((a)[1]), "r"((a)[2]), "r"((a)[3]), \
          "r"((b)[0]), "r"((b)[1]))

enum { E_NONE = 0, E_BROW = 1, E_RES = 2, E_BN = 3, E_BNRES = 4 };

// ===========================================================================
// split-plane fp32 -> (hi, lo) bf16 planes
// ===========================================================================
__global__ __launch_bounds__(256) void k_cvt(const float* __restrict__ X,
                                             bf16* __restrict__ H,
                                             bf16* __restrict__ L, int n4)
{
    const int i = blockIdx.x * 256 + threadIdx.x;
    if (i >= n4) return;
    float4 v = *(const float4*)(X + (size_t)i * 4);
    bf16 h0,l0,h1,l1,h2,l2,h3,l3;
    spl(v.x,h0,l0); spl(v.y,h1,l1); spl(v.z,h2,l2); spl(v.w,h3,l3);
    *(uint2*)(H + (size_t)i * 4) = make_uint2(pk(h0,h1), pk(h2,h3));
    *(uint2*)(L + (size_t)i * 4) = make_uint2(pk(l0,l1), pk(l2,l3));
}

// ===========================================================================
// HMMA GEMM on preconverted bf16 planes: D[m][n] = sum_k A[m][k]*B[k][n]
// tile 128x64x32, 8 warps (4x2), warp tile 32x32, 2 CTAs/SM, cp.async loads.
// ===========================================================================
template <int EPI, bool TA, bool I2C, bool OF32, bool OBF>
__global__ __launch_bounds__(256, 2) void k_mm(
    const bf16* __restrict__ Ah, const bf16* __restrict__ Al,
    size_t Abs, int lda,
    const bf16* __restrict__ Bh, const bf16* __restrict__ Bl,
    size_t Bbs, int ldb, int Ktot,
    float* __restrict__ D, bf16* __restrict__ Dh, bf16* __restrict__ Dl,
    size_t Dbs, int ldd,
    const float* __restrict__ bias,
    const float* __restrict__ Res, size_t Rbs,
    const float* __restrict__ bns, const float* __restrict__ bnb,
    const float* __restrict__ bnm, const float* __restrict__ bnv)
{
    extern __shared__ char sm[];
    constexpr int ASZ = TA ? (BKT * AM_PAD * 2) : (BMT * AK_PAD * 2);
    constexpr int BSZ = BKT * BN_PAD * 2;
    constexpr int STG = 2 * ASZ + 2 * BSZ;

    const int tid = threadIdx.x, wid = tid >> 5, lane = tid & 31;
    const int wm = wid & 3, wn = wid >> 2;
    const int colT = blockIdx.x * BNT, rowT = blockIdx.y * BMT, bz = blockIdx.z;
    const uint32_t su = smem_u32(sm);

    const bf16* Ah_b = Ah + (size_t)bz * Abs;
    const bf16* Al_b = Al + (size_t)bz * Abs;
    const bf16* Bh_b = Bh + (size_t)bz * Bbs;
    const bf16* Bl_b = Bl + (size_t)bz * Bbs;

    float acc[2][4][4];
    #pragma unroll
    for (int i = 0; i < 2; i++)
        #pragma unroll
        for (int j = 0; j < 4; j++)
            #pragma unroll
            for (int q = 0; q < 4; q++) acc[i][j][q] = 0.f;

    // cp.async tile loaders (A always; B when !I2C)
    auto cpa = [&](int k0, int s) {
        const uint32_t base = su + s * STG;
        if constexpr (!TA) {
            #pragma unroll
            for (int i = 0; i < 2; i++) {
                const int idx = tid + (i << 8);      // 0..511
                const int row = idx >> 2, c4 = idx & 3;
                const size_t so = (size_t)(rowT + row) * lda + k0 + c4 * 8;
                const uint32_t d = base + (uint32_t)row * (AK_PAD * 2) + c4 * 16;
                CPA(d, Ah_b + so);
                CPA(d + ASZ, Al_b + so);
            }
        } else {
            #pragma unroll
            for (int i = 0; i < 2; i++) {
                const int idx = tid + (i << 8);
                const int row = idx >> 4, c16 = idx & 15;
                const size_t so = (size_t)(k0 + row) * lda + rowT + c16 * 8;
                const uint32_t d = base + (uint32_t)row * (AM_PAD * 2) + c16 * 16;
                CPA(d, Ah_b + so);
                CPA(d + ASZ, Al_b + so);
            }
        }
        if constexpr (!I2C) {
            const int row = tid >> 3, c8 = tid & 7;
            const size_t so = (size_t)(k0 + row) * ldb + colT + c8 * 8;
            const uint32_t d = base + 2 * ASZ + (uint32_t)row * (BN_PAD * 2) + c8 * 16;
            CPA(d, Bh_b + so);
            CPA(d + BSZ, Bl_b + so);
        }
    };

    // im2col gather (regs) + deferred STS for conv B
    unsigned short bh_[8], bl_[8];
    auto ldB_i2c = [&](int k0) {
        const unsigned short* BhU = (const unsigned short*)Bh_b;
        const unsigned short* BlU = (const unsigned short*)Bl_b;
        #pragma unroll
        for (int j = 0; j < 2; j++) {
            const int kg = k0 + (tid >> 4) + j * 16;
            const int c  = kg / 9;
            const int r  = kg - c * 9;
            const int ky = r / 3;
            const int kx = r - ky * 3;
            const size_t cb = (size_t)c * NPIX;
            #pragma unroll
            for (int u = 0; u < 4; u++) {
                const int p = colT + ((tid & 15) << 2) + u;
                const int y = p / WWW, x = p - y * WWW;
                const int sy = y + ky - 1, sx = x + kx - 1;
                const bool ok = (unsigned)sy < (unsigned)HHH &&
                                (unsigned)sx < (unsigned)WWW;
                const size_t off = cb + sy * WWW + sx;
                bh_[j * 4 + u] = ok ? BhU[off] : 0;
                bl_[j * 4 + u] = ok ? BlU[off] : 0;
            }
        }
    };
    auto stsB_i2c = [&](int s) {
        char* hi = sm + s * STG + 2 * ASZ;
        char* lo = hi + BSZ;
        #pragma unroll
        for (int j = 0; j < 2; j++) {
            const uint32_t off = (uint32_t)((tid >> 4) + j * 16) * (BN_PAD * 2)
                                 + ((tid & 15) << 3);
            *(uint2*)(hi + off) = make_uint2(
                (uint32_t)bh_[j*4+0] | ((uint32_t)bh_[j*4+1] << 16),
                (uint32_t)bh_[j*4+2] | ((uint32_t)bh_[j*4+3] << 16));
            *(uint2*)(lo + off) = make_uint2(
                (uint32_t)bl_[j*4+0] | ((uint32_t)bl_[j*4+1] << 16),
                (uint32_t)bl_[j*4+2] | ((uint32_t)bl_[j*4+3] << 16));
        }
    };

    // ldmatrix offsets
    const int mtx = lane >> 3, r8 = lane & 7;
    uint32_t aoff[2][2];
    #pragma unroll
    for (int mi = 0; mi < 2; mi++)
        #pragma unroll
        for (int ks = 0; ks < 2; ks++) {
            if constexpr (!TA) {
                const int row = wm * 32 + mi * 16 + (mtx & 1) * 8 + r8;
                const int kc  = ks * 16 + (mtx >> 1) * 8;
                aoff[mi][ks] = (uint32_t)row * (AK_PAD * 2) + kc * 2;
            } else {
                const int kk = ks * 16 + (mtx >> 1) * 8 + r8;
                const int mm = wm * 32 + mi * 16 + (mtx & 1) * 8;
                aoff[mi][ks] = (uint32_t)kk * (AM_PAD * 2) + mm * 2;
            }
        }
    uint32_t boff[2][2];
    #pragma unroll
    for (int ni2 = 0; ni2 < 2; ni2++)
        #pragma unroll
        for (int ks = 0; ks < 2; ks++) {
            const int kb = ks * 16 + (mtx & 1) * 8 + r8;
            const int nb = wn * 32 + ni2 * 16 + (mtx >> 1) * 8;
            boff[ni2][ks] = (uint32_t)kb * (BN_PAD * 2) + nb * 2;
        }

    // prologue
    cpa(0, 0);
    CPA_COMMIT();
    if constexpr (I2C) { ldB_i2c(0); stsB_i2c(0); }
    CPA_WAIT0();
    __syncthreads();

    const int nch = Ktot / BKT;
    for (int i = 0; i < nch; i++) {
        const int s = i & 1;
        if (i + 1 < nch) {
            cpa((i + 1) * BKT, s ^ 1);
            CPA_COMMIT();
            if constexpr (I2C) ldB_i2c((i + 1) * BKT);
        }

        const uint32_t aHi = su + s * STG;
        const uint32_t aLo = aHi + ASZ;
        const uint32_t bHi = aHi + 2 * ASZ;
        const uint32_t bLo = bHi + BSZ;

        #pragma unroll
        for (int ks = 0; ks < 2; ks++) {
            uint32_t ah[2][4], al[2][4];
            #pragma unroll
            for (int mi = 0; mi < 2; mi++) {
                if constexpr (!TA) {
                    LDMX4(ah[mi], aHi + aoff[mi][ks]);
                    LDMX4(al[mi], aLo + aoff[mi][ks]);
                } else {
                    LDMX4T(ah[mi], aHi + aoff[mi][ks]);
                    LDMX4T(al[mi], aLo + aoff[mi][ks]);
                }
            }
            #pragma unroll
            for (int ni2 = 0; ni2 < 2; ni2++) {
                uint32_t bh[4], bl[4];
                LDMX4T(bh, bHi + boff[ni2][ks]);
                LDMX4T(bl, bLo + boff[ni2][ks]);
                #pragma unroll
                for (int mi = 0; mi < 2; mi++) {
                    #pragma unroll
                    for (int nf = 0; nf < 2; nf++) {
                        float* ac = acc[mi][ni2 * 2 + nf];
                        MMA16816(ac, ah[mi], bh + nf * 2);
                        MMA16816(ac, ah[mi], bl + nf * 2);
                        MMA16816(ac, al[mi], bh + nf * 2);
                    }
                }
            }
        }
        if (i + 1 < nch) {
            if constexpr (I2C) stsB_i2c(s ^ 1);
            CPA_WAIT0();
        }
        __syncthreads();
    }

    // ---- epilogue ----
    #pragma unroll
    for (int mi = 0; mi < 2; mi++) {
        const int r = rowT + wm * 32 + mi * 16 + (lane >> 2);
        float ba = 0.f, bb_ = 0.f, inva = 0.f, beta_a = 0.f, invb = 0.f, beta_b = 0.f;
        if (EPI == E_BROW) { ba = bias[r]; bb_ = bias[r + 8]; }
        if (EPI == E_BN || EPI == E_BNRES) {
            inva = bns[r] * rsqrtf(bnv[r] + EPSB);
            beta_a = bnb[r] - bnm[r] * inva;
            invb = bns[r + 8] * rsqrtf(bnv[r + 8] + EPSB);
            beta_b = bnb[r + 8] - bnm[r + 8] * invb;
        }
        const size_t ro0 = (size_t)bz * Dbs + (size_t)r * ldd;
        const size_t ro1 = ro0 + 8 * (size_t)ldd;
        const float* rs0 = (EPI == E_RES || EPI == E_BNRES)
                               ? Res + (size_t)bz * Rbs + (size_t)r * ldd : nullptr;
        const float* rs1 = rs0 ? rs0 + 8 * (size_t)ldd : nullptr;
        #pragma unroll
        for (int ni = 0; ni < 4; ni++) {
            const int c = colT + wn * 32 + ni * 8 + ((lane & 3) << 1);
            float v0 = acc[mi][ni][0], v1 = acc[mi][ni][1];
            float v2 = acc[mi][ni][2], v3 = acc[mi][ni][3];
            if (EPI == E_BROW) {
                v0 += ba; v1 += ba; v2 += bb_; v3 += bb_;
            } else if (EPI == E_RES) {
                float2 f0 = *(const float2*)(rs0 + c);
                float2 f1 = *(const float2*)(rs1 + c);
                v0 += f0.x; v1 += f0.y; v2 += f1.x; v3 += f1.y;
            } else if (EPI == E_BN) {
                v0 = fmaxf(v0 * inva + beta_a, 0.f);
                v1 = fmaxf(v1 * inva + beta_a, 0.f);
                v2 = fmaxf(v2 * invb + beta_b, 0.f);
                v3 = fmaxf(v3 * invb + beta_b, 0.f);
            } else if (EPI == E_BNRES) {
                float2 f0 = *(const float2*)(rs0 + c);
                float2 f1 = *(const float2*)(rs1 + c);
                v0 = fmaxf(v0 * inva + beta_a + f0.x, 0.f) + f0.x;
                v1 = fmaxf(v1 * inva + beta_a + f0.y, 0.f) + f0.y;
                v2 = fmaxf(v2 * invb + beta_b + f1.x, 0.f) + f1.x;
                v3 = fmaxf(v3 * invb + beta_b + f1.y, 0.f) + f1.y;
            }
            if (OF32) {
                *(float2*)(D + ro0 + c) = make_float2(v0, v1);
                *(float2*)(D + ro1 + c) = make_float2(v2, v3);
            }
            if (OBF) {
                wr_bf(Dh, Dl, ro0 + c, v0, v1);
                wr_bf(Dh, Dl, ro1 + c, v2, v3);
            }
        }
    }
}

// ===========================================================================
// Row softmax; reads fp32 scores, writes split-bf16 attn planes
// ===========================================================================
__global__ __launch_bounds__(256) void k_softmax(const float* __restrict__ S,
                                                 bf16* __restrict__ Ah,
                                                 bf16* __restrict__ Al)
{
    const size_t base = (size_t)blockIdx.x * NPIX;
    const float* p = S + base;
    const int tid = threadIdx.x;
    float v[9];
    float mx = -1e30f;
    #pragma unroll
    for (int i = 0; i < 9; i++) {
        v[i] = p[tid + (i << 8)];
        mx = fmaxf(mx, v[i]);
    }
    __shared__ float red[8];
    #pragma unroll
    for (int o = 16; o > 0; o >>= 1)
        mx = fmaxf(mx, __shfl_xor_sync(0xffffffffu, mx, o));
    if ((tid & 31) == 0) red[tid >> 5] = mx;
    __syncthreads();
    float m2 = red[0];
    #pragma unroll
    for (int i = 1; i < 8; i++) m2 = fmaxf(m2, red[i]);
    __syncthreads();
    float s = 0.f;
    #pragma unroll
    for (int i = 0; i < 9; i++) { v[i] = __expf(v[i] - m2); s += v[i]; }
    #pragma unroll
    for (int o = 16; o > 0; o >>= 1)
        s += __shfl_xor_sync(0xffffffffu, s, o);
    if ((tid & 31) == 0) red[tid >> 5] = s;
    __syncthreads();
    float s2 = 0.f;
    #pragma unroll
    for (int i = 0; i < 8; i++) s2 += red[i];
    const float inv = 1.0f / s2;
    #pragma unroll
    for (int i = 0; i < 9; i++) {
        bf16 h, l;
        spl(v[i] * inv, h, l);
        Ah[base + tid + (i << 8)] = h;
        Al[base + tid + (i << 8)] = l;
    }
}

// ===========================================================================
// Host launcher
// ===========================================================================
extern "C" void kernel_launch(void* const* d_in, const int* in_sizes, int n_in,
                              void* d_out, int out_size)
{
    (void)in_sizes; (void)n_in; (void)out_size;
    const float* F_b  = (const float*)d_in[0];
    const float* F_a  = (const float*)d_in[1];
    const float* qw   = (const float*)d_in[2];
    const float* qb   = (const float*)d_in[3];
    const float* kw   = (const float*)d_in[4];
    const float* kb   = (const float*)d_in[5];
    const float* vw   = (const float*)d_in[6];
    const float* vb   = (const float*)d_in[7];
    const float* c1w  = (const float*)d_in[8];
    const float* bn1s = (const float*)d_in[9];
    const float* bn1b = (const float*)d_in[10];
    const float* bn1m = (const float*)d_in[11];
    const float* bn1v = (const float*)d_in[12];
    const float* c2w  = (const float*)d_in[13];
    const float* bn2s = (const float*)d_in[14];
    const float* bn2b = (const float*)d_in[15];
    const float* bn2m = (const float*)d_in[16];
    const float* bn2v = (const float*)d_in[17];
    float* out = (float*)d_out;

    float *scores, *fused;
    bf16 *Fbh,*Fbl,*Fah,*Fal,*qwh,*qwl,*kwh,*kwl,*vwh,*vwl;
    bf16 *c1h,*c1l,*c2h,*c2l,*Qh,*Ql,*Kh,*Kl,*Vh,*Vl;
    bf16 *Ath,*Atl,*Fh,*Fl,*th,*tl;
    cudaGetSymbolAddress((void**)&scores, g_scores);
    cudaGetSymbolAddress((void**)&fused,  g_fused);
    cudaGetSymbolAddress((void**)&Fbh, g_Fbh); cudaGetSymbolAddress((void**)&Fbl, g_Fbl);
    cudaGetSymbolAddress((void**)&Fah, g_Fah); cudaGetSymbolAddress((void**)&Fal, g_Fal);
    cudaGetSymbolAddress((void**)&qwh, g_qwh); cudaGetSymbolAddress((void**)&qwl, g_qwl);
    cudaGetSymbolAddress((void**)&kwh, g_kwh); cudaGetSymbolAddress((void**)&kwl, g_kwl);
    cudaGetSymbolAddress((void**)&vwh, g_vwh); cudaGetSymbolAddress((void**)&vwl, g_vwl);
    cudaGetSymbolAddress((void**)&c1h, g_c1h); cudaGetSymbolAddress((void**)&c1l, g_c1l);
    cudaGetSymbolAddress((void**)&c2h, g_c2h); cudaGetSymbolAddress((void**)&c2l, g_c2l);
    cudaGetSymbolAddress((void**)&Qh,  g_Qh);  cudaGetSymbolAddress((void**)&Ql,  g_Ql);
    cudaGetSymbolAddress((void**)&Kh,  g_Kh);  cudaGetSymbolAddress((void**)&Kl,  g_Kl);
    cudaGetSymbolAddress((void**)&Vh,  g_Vh);  cudaGetSymbolAddress((void**)&Vl,  g_Vl);
    cudaGetSymbolAddress((void**)&Ath, g_Ath); cudaGetSymbolAddress((void**)&Atl, g_Atl);
    cudaGetSymbolAddress((void**)&Fh,  g_Fh);  cudaGetSymbolAddress((void**)&Fl,  g_Fl);
    cudaGetSymbolAddress((void**)&th,  g_th);  cudaGetSymbolAddress((void**)&tl,  g_tl);

    const int SMEM_MK = 2 * (2 * BMT * AK_PAD * 2 + 2 * BKT * BN_PAD * 2); // 59392
    const int SMEM_KM = 2 * (2 * BKT * AM_PAD * 2 + 2 * BKT * BN_PAD * 2); // 53248

    cudaFuncSetAttribute((const void*)k_mm<E_BROW,  false, false, false, true >, cudaFuncAttributeMaxDynamicSharedMemorySize, SMEM_MK);
    cudaFuncSetAttribute((const void*)k_mm<E_NONE,  true,  false, true,  false>, cudaFuncAttributeMaxDynamicSharedMemorySize, SMEM_KM);
    cudaFuncSetAttribute((const void*)k_mm<E_RES,   false, false, true,  true >, cudaFuncAttributeMaxDynamicSharedMemorySize, SMEM_MK);
    cudaFuncSetAttribute((const void*)k_mm<E_BN,    false, true,  false, true >, cudaFuncAttributeMaxDynamicSharedMemorySize, SMEM_MK);
    cudaFuncSetAttribute((const void*)k_mm<E_BNRES, false, true,  true,  false>, cudaFuncAttributeMaxDynamicSharedMemorySize, SMEM_MK);

    dim3 blk(256);
    dim3 gFeat(NPIX / BNT, CCH / BMT, BBATCH);   // (36, 2, 16)
    dim3 gScor(NPIX / BNT, NPIX / BMT, BBATCH);  // (36, 18, 16)
    const size_t FS = (size_t)CCH * NPIX;
    const size_t AS = (size_t)NPIX * NPIX;

    // ---- preconvert inputs/weights to split-bf16 planes ----
    k_cvt<<<(int)(FSZ/4/256), blk>>>(F_b, Fbh, Fbl, (int)(FSZ/4));
    k_cvt<<<(int)(FSZ/4/256), blk>>>(F_a, Fah, Fal, (int)(FSZ/4));
    k_cvt<<<CCH*CCH/4/256, blk>>>(qw, qwh, qwl, CCH*CCH/4);
    k_cvt<<<CCH*CCH/4/256, blk>>>(kw, kwh, kwl, CCH*CCH/4);
    k_cvt<<<CCH*CCH/4/256, blk>>>(vw, vwh, vwl, CCH*CCH/4);
    k_cvt<<<CCH*KCONV/4/256, blk>>>(c1w, c1h, c1l, CCH*KCONV/4);
    k_cvt<<<CCH*KCONV/4/256, blk>>>(c2w, c2h, c2l, CCH*KCONV/4);

    // ---- Q, K, V ----
    k_mm<E_BROW, false, false, false, true><<<gFeat, blk, SMEM_MK>>>(
        qwh, qwl, 0, CCH, Fbh, Fbl, FS, NPIX, CCH,
        nullptr, Qh, Ql, FS, NPIX, qb, nullptr, 0,
        nullptr, nullptr, nullptr, nullptr);
    k_mm<E_BROW, false, false, false, true><<<gFeat, blk, SMEM_MK>>>(
        kwh, kwl, 0, CCH, Fah, Fal, FS, NPIX, CCH,
        nullptr, Kh, Kl, FS, NPIX, kb, nullptr, 0,
        nullptr, nullptr, nullptr, nullptr);
    k_mm<E_BROW, false, false, false, true><<<gFeat, blk, SMEM_MK>>>(
        vwh, vwl, 0, CCH, Fah, Fal, FS, NPIX, CCH,
        nullptr, Vh, Vl, FS, NPIX, vb, nullptr, 0,
        nullptr, nullptr, nullptr, nullptr);

    // ---- scores[n][m] = sum_c K[c][n] * Q[c][m] (fp32 out) ----
    k_mm<E_NONE, true, false, true, false><<<gScor, blk, SMEM_KM>>>(
        Kh, Kl, FS, NPIX, Qh, Ql, FS, NPIX, CCH,
        scores, nullptr, nullptr, AS, NPIX, nullptr, nullptr, 0,
        nullptr, nullptr, nullptr, nullptr);

    // ---- softmax -> split-bf16 attn ----
    k_softmax<<<BBATCH * NPIX, blk>>>(scores, Ath, Atl);

    // ---- fused = V @ attn + F_b (fp32 + planes) ----
    k_mm<E_RES, false, false, true, true><<<gFeat, blk, SMEM_MK>>>(
        Vh, Vl, FS, NPIX, Ath, Atl, AS, NPIX, NPIX,
        fused, Fh, Fl, FS, NPIX, nullptr, F_b, FS,
        nullptr, nullptr, nullptr, nullptr);

    // ---- conv1 + bn1 + relu -> tmp planes ----
    k_mm<E_BN, false, true, false, true><<<gFeat, blk, SMEM_MK>>>(
        c1h, c1l, 0, KCONV, Fh, Fl, FS, 0, KCONV,
        nullptr, th, tl, FS, NPIX, nullptr, nullptr, 0,
        bn1s, bn1b, bn1m, bn1v);
    // ---- conv2 + bn2 + residual -> out ----
    k_mm<E_BNRES, false, true, true, false><<<gFeat, blk, SMEM_MK>>>(
        c2h, c2l, 0, KCONV, th, tl, FS, 0, KCONV,
        out, nullptr, nullptr, FS, NPIX, nullptr, fused, FS,
        bn2s, bn2b, bn2m, bn2v);
}